// round 7
// baseline (speedup 1.0000x reference)
#include <cuda_runtime.h>
#include <cuda_fp16.h>
#include <cstdint>
#include <cstddef>

#define N_NODES 50000
#define NE      640000
#define ET      (NE + N_NODES)   // edges + self loops = 690000
#define D_IN    128
#define HID     64
#define HEADS   3
#define SLOPE   0.2f
#define EPS     1e-16f

#define SCAN_BLK 1024
#define NBLK     ((N_NODES + SCAN_BLK - 1) / SCAN_BLK)   // 49

// ---------------- scratch (no allocations; referenced ONLY from device code) ----------------
__device__ __half g_xwh[(size_t)N_NODES * HEADS * HID]; // fp16 features (xw1, then xw2)
__device__ __half g_h1h[(size_t)N_NODES * HEADS * HID]; // layer-1 output (fp16, GEMM2 input)
__device__ float  g_asrc[N_NODES * HEADS];
__device__ float  g_adst[N_NODES * HEADS];
__device__ int    g_counts[N_NODES];
__device__ int    g_offsets[N_NODES + 1];
__device__ int    g_cursor[N_NODES];
__device__ int    g_csr_src[ET];
__device__ int    g_blocksums[NBLK];
__device__ int    g_blockbase[NBLK];
__device__ int    g_is64;

// ---------------- edge-index dtype probe ----------------
// int64 (<2^31, LE): every odd 32-bit word is 0. int32: odd words are random ids.
__global__ void probe_kernel(const int* __restrict__ ei32) {
    __shared__ int s_or[256];
    int tid = threadIdx.x;
    int acc = 0;
    for (int i = tid; i < 2048; i += 256) acc |= ei32[2 * i + 1];
    s_or[tid] = acc;
    __syncthreads();
    for (int s = 128; s > 0; s >>= 1) {
        if (tid < s) s_or[tid] |= s_or[tid + s];
        __syncthreads();
    }
    if (tid == 0) g_is64 = (s_or[0] == 0) ? 1 : 0;
}

__device__ __forceinline__ int edge_at(const void* ei, long long idx) {
    if (g_is64) return (int)((const long long*)ei)[idx];
    return ((const int*)ei)[idx];
}

// ---------------- CSR build ----------------
__global__ void zero_counts_kernel() {
    int i = blockIdx.x * blockDim.x + threadIdx.x;
    if (i < N_NODES) g_counts[i] = 0;
}

__global__ void count_kernel(const void* __restrict__ ei) {
    int e = blockIdx.x * blockDim.x + threadIdx.x;
    if (e >= ET) return;
    int dst = (e < NE) ? edge_at(ei, (long long)NE + e) : (e - NE);
    atomicAdd(&g_counts[dst], 1);
}

__global__ void scan_part_kernel() {
    __shared__ int warp_sums[32];
    int tid = threadIdx.x, lane = tid & 31, wid = tid >> 5;
    int idx = blockIdx.x * SCAN_BLK + tid;
    int v = (idx < N_NODES) ? g_counts[idx] : 0;
    int x = v;
    #pragma unroll
    for (int o = 1; o < 32; o <<= 1) {
        int y = __shfl_up_sync(0xffffffffu, x, o);
        if (lane >= o) x += y;
    }
    if (lane == 31) warp_sums[wid] = x;
    __syncthreads();
    if (wid == 0) {
        int w = warp_sums[lane];
        #pragma unroll
        for (int o = 1; o < 32; o <<= 1) {
            int y = __shfl_up_sync(0xffffffffu, w, o);
            if (lane >= o) w += y;
        }
        warp_sums[lane] = w;
    }
    __syncthreads();
    int warp_off = (wid > 0) ? warp_sums[wid - 1] : 0;
    int incl = x + warp_off;
    if (idx < N_NODES) g_offsets[idx] = incl - v;   // local exclusive
    if (tid == SCAN_BLK - 1) g_blocksums[blockIdx.x] = incl;
}

__global__ void scan_sums_kernel() {
    int tid = threadIdx.x;                 // 64 threads
    __shared__ int s[NBLK];
    if (tid < NBLK) s[tid] = g_blocksums[tid];
    __syncthreads();
    if (tid == 0) {
        int run = 0;
        for (int i = 0; i < NBLK; i++) { g_blockbase[i] = run; run += s[i]; }
        g_offsets[N_NODES] = run;
    }
}

__global__ void scan_fixup_kernel() {
    int idx = blockIdx.x * SCAN_BLK + threadIdx.x;
    if (idx < N_NODES) {
        int v = g_offsets[idx] + g_blockbase[blockIdx.x];
        g_offsets[idx] = v;
        g_cursor[idx] = v;
    }
}

__global__ void scatter_kernel(const void* __restrict__ ei) {
    int e = blockIdx.x * blockDim.x + threadIdx.x;
    if (e >= ET) return;
    int src, dst;
    if (e < NE) {
        src = edge_at(ei, e);
        dst = edge_at(ei, (long long)NE + e);
    } else {
        src = e - NE; dst = e - NE;
    }
    int pos = atomicAdd(&g_cursor[dst], 1);
    g_csr_src[pos] = src;
}

// ---------------- fp16 tensor-core GEMM -> fp16 feature buffer ----------------
// g_xwh[M,N] = half(A[M,K] @ B[K,N]), fp32 accumulate. BM=128, BN=64, BK=32;
// 8 warps 4(m)x2(n); 32x32 per warp via 2x4 m16n8k16 atoms.
// fp16 inputs have the same 11-bit mantissa as tf32; accumulation is fp32.
#define ASTR 40   // smem row stride in halves (80 B): (20g+t) mod 32 distinct -> conflict-free

__device__ __forceinline__ void mma_f16(float* d, const uint32_t* a, const uint32_t* b) {
    asm volatile(
        "mma.sync.aligned.m16n8k16.row.col.f32.f16.f16.f32 "
        "{%0,%1,%2,%3}, {%4,%5,%6,%7}, {%8,%9}, {%0,%1,%2,%3};\n"
        : "+f"(d[0]), "+f"(d[1]), "+f"(d[2]), "+f"(d[3])
        : "r"(a[0]), "r"(a[1]), "r"(a[2]), "r"(a[3]), "r"(b[0]), "r"(b[1]));
}

template <bool A_HALF>
__global__ __launch_bounds__(256)
void gemm_f16_kernel(const float* __restrict__ Af, const float* __restrict__ B,
                     int M, int N, int K) {
    __shared__ __half As[128 * ASTR];
    __shared__ __half Bs[64 * ASTR];
    int tid = threadIdx.x;
    int lane = tid & 31, wid = tid >> 5;
    int warp_m = wid & 3, warp_n = wid >> 2;
    int m0 = blockIdx.x * 128, n0 = blockIdx.y * 64;
    int g = lane >> 2, t = lane & 3;

    float acc[2][4][4];
    #pragma unroll
    for (int i = 0; i < 2; i++)
        #pragma unroll
        for (int j = 0; j < 4; j++)
            #pragma unroll
            for (int q = 0; q < 4; q++) acc[i][j][q] = 0.f;

    const __half* Ah = A_HALF ? (const __half*)g_h1h : nullptr;

    for (int k0 = 0; k0 < K; k0 += 32) {
        // stage A: 128x32 halves; each thread does 4 elements x 4 iters
        #pragma unroll
        for (int s = tid; s < 1024; s += 256) {
            int r = s >> 3, c = (s & 7) * 4;
            __half2 h01, h23;
            if (m0 + r < M) {
                if (A_HALF) {
                    const __half* ap = Ah + (size_t)(m0 + r) * K + k0 + c;
                    h01 = *(const __half2*)ap;
                    h23 = *(const __half2*)(ap + 2);
                } else {
                    float4 v = *(const float4*)(Af + (size_t)(m0 + r) * K + k0 + c);
                    h01 = __floats2half2_rn(v.x, v.y);
                    h23 = __floats2half2_rn(v.z, v.w);
                }
            } else {
                h01 = __floats2half2_rn(0.f, 0.f);
                h23 = h01;
            }
            *(__half2*)&As[r * ASTR + c] = h01;
            *(__half2*)&As[r * ASTR + c + 2] = h23;
        }
        // stage B transposed: Bs[n][k], k contiguous (for col-major fragment loads)
        #pragma unroll
        for (int s = tid; s < 512; s += 256) {
            int kk = s >> 4, n = (s & 15) * 4;
            float4 v = *(const float4*)(B + (size_t)(k0 + kk) * N + n0 + n);
            Bs[(n + 0) * ASTR + kk] = __float2half_rn(v.x);
            Bs[(n + 1) * ASTR + kk] = __float2half_rn(v.y);
            Bs[(n + 2) * ASTR + kk] = __float2half_rn(v.z);
            Bs[(n + 3) * ASTR + kk] = __float2half_rn(v.w);
        }
        __syncthreads();
        #pragma unroll
        for (int k16 = 0; k16 < 32; k16 += 16) {
            uint32_t af[2][4];
            #pragma unroll
            for (int am = 0; am < 2; am++) {
                int r0 = warp_m * 32 + am * 16 + g;
                af[am][0] = *(const uint32_t*)&As[(r0)     * ASTR + k16 + 2 * t];
                af[am][1] = *(const uint32_t*)&As[(r0 + 8) * ASTR + k16 + 2 * t];
                af[am][2] = *(const uint32_t*)&As[(r0)     * ASTR + k16 + 2 * t + 8];
                af[am][3] = *(const uint32_t*)&As[(r0 + 8) * ASTR + k16 + 2 * t + 8];
            }
            uint32_t bf[4][2];
            #pragma unroll
            for (int an = 0; an < 4; an++) {
                int nn = warp_n * 32 + an * 8 + g;
                bf[an][0] = *(const uint32_t*)&Bs[nn * ASTR + k16 + 2 * t];
                bf[an][1] = *(const uint32_t*)&Bs[nn * ASTR + k16 + 2 * t + 8];
            }
            #pragma unroll
            for (int am = 0; am < 2; am++)
                #pragma unroll
                for (int an = 0; an < 4; an++)
                    mma_f16(acc[am][an], af[am], bf[an]);
        }
        __syncthreads();
    }

    // store C as fp16
    #pragma unroll
    for (int am = 0; am < 2; am++) {
        int r0 = m0 + warp_m * 32 + am * 16 + g;
        #pragma unroll
        for (int an = 0; an < 4; an++) {
            int cn = n0 + warp_n * 32 + an * 8 + 2 * t;
            if (r0 < M)
                *(__half2*)&g_xwh[(size_t)r0 * N + cn] =
                    __floats2half2_rn(acc[am][an][0], acc[am][an][1]);
            if (r0 + 8 < M)
                *(__half2*)&g_xwh[(size_t)(r0 + 8) * N + cn] =
                    __floats2half2_rn(acc[am][an][2], acc[am][an][3]);
        }
    }
}

// ---------------- per-node attention coefficients (reads fp16 features) ----------------
__global__ void alpha_kernel(const float* __restrict__ a_src,
                             const float* __restrict__ a_dst, int H) {
    int warp = (blockIdx.x * blockDim.x + threadIdx.x) >> 5;
    int lane = threadIdx.x & 31;
    if (warp >= N_NODES * H) return;
    int n = warp / H, h = warp % H;
    const __half* row = g_xwh + (size_t)n * H * HID + h * HID;
    const float* asv = a_src + h * HID;
    const float* adv = a_dst + h * HID;
    float r1 = __half2float(row[lane]);
    float r2 = __half2float(row[lane + 32]);
    float s1 = r1 * asv[lane] + r2 * asv[lane + 32];
    float s2 = r1 * adv[lane] + r2 * adv[lane + 32];
    #pragma unroll
    for (int o = 16; o > 0; o >>= 1) {
        s1 += __shfl_xor_sync(0xffffffffu, s1, o);
        s2 += __shfl_xor_sync(0xffffffffu, s2, o);
    }
    if (lane == 0) {
        g_asrc[n * H + h] = s1;
        g_adst[n * H + h] = s2;
    }
}

// ---------------- warp-centric fused softmax + aggregation ----------------
// One warp per (node, head). Lane j computes exp for edge j (coalesced);
// shfl-broadcast inner loop gathers half2 features with unroll-8 MLP.
// Max-subtraction skipped (identical result; logits bounded).
// OUT_HALF: write g_h1h as fp16 (layer 1); else write out_p as fp32 (layer 2).
template <int H, int C, bool OUT_HALF>
__global__ __launch_bounds__(256)
void aggregate_warp_kernel(const float* __restrict__ bias,
                           float* __restrict__ out_p) {
    int gw = (blockIdx.x * blockDim.x + threadIdx.x) >> 5;
    int lane = threadIdx.x & 31;
    if (gw >= N_NODES * H) return;
    int n = gw / H, h = gw % H;
    int beg = g_offsets[n], end = g_offsets[n + 1];
    float adst_n = g_adst[n * H + h];

    float2 acc = make_float2(0.f, 0.f);
    float denom = 0.f;
    const __half* xwh = g_xwh;

    for (int base = beg; base < end; base += 32) {
        int j = base + lane;
        bool valid = j < end;
        int s = valid ? g_csr_src[j] : 0;
        float e = 0.f;
        if (valid) {
            float v = g_asrc[s * H + h] + adst_n;
            v = (v > 0.f) ? v : SLOPE * v;
            e = __expf(v);
        }
        denom += e;
        int ne = min(32, end - base);
        int jj = 0;
        for (; jj + 8 <= ne; jj += 8) {
            float ev[8]; int sv[8];
            #pragma unroll
            for (int q = 0; q < 8; q++) {
                ev[q] = __shfl_sync(0xffffffffu, e, jj + q);
                sv[q] = __shfl_sync(0xffffffffu, s, jj + q);
            }
            float2 f[8];
            #pragma unroll
            for (int q = 0; q < 8; q++)
                f[q] = __half22float2(
                    *(const __half2*)&xwh[(size_t)sv[q] * (H * C) + h * C + 2 * lane]);
            #pragma unroll
            for (int q = 0; q < 8; q++) {
                acc.x += ev[q] * f[q].x;
                acc.y += ev[q] * f[q].y;
            }
        }
        for (; jj < ne; jj++) {
            float ee = __shfl_sync(0xffffffffu, e, jj);
            int   ss = __shfl_sync(0xffffffffu, s, jj);
            float2 f = __half22float2(
                *(const __half2*)&xwh[(size_t)ss * (H * C) + h * C + 2 * lane]);
            acc.x += ee * f.x; acc.y += ee * f.y;
        }
    }
    #pragma unroll
    for (int o = 16; o > 0; o >>= 1)
        denom += __shfl_xor_sync(0xffffffffu, denom, o);
    float inv = 1.f / (denom + EPS);
    int c0 = h * C + 2 * lane;
    float rx = fmaxf(acc.x * inv + bias[c0], 0.f);
    float ry = fmaxf(acc.y * inv + bias[c0 + 1], 0.f);
    if (OUT_HALF) {
        *(__half2*)&g_h1h[(size_t)n * (H * C) + c0] = __floats2half2_rn(rx, ry);
    } else {
        *(float2*)&out_p[(size_t)n * (H * C) + c0] = make_float2(rx, ry);
    }
}

// ---------------- launch ----------------
extern "C" void kernel_launch(void* const* d_in, const int* in_sizes, int n_in,
                              void* d_out, int out_size) {
    const float* x   = (const float*)d_in[0];
    const void*  ei  = d_in[1];                 // int32 or int64 (probed on device)
    const float* W1  = (const float*)d_in[2];
    const float* as1 = (const float*)d_in[3];
    const float* ad1 = (const float*)d_in[4];
    const float* b1  = (const float*)d_in[5];
    const float* W2  = (const float*)d_in[6];
    const float* as2 = (const float*)d_in[7];
    const float* ad2 = (const float*)d_in[8];
    const float* b2  = (const float*)d_in[9];
    float*       out = (float*)d_out;

    const int TB = 256;
    int gridN = (N_NODES + TB - 1) / TB;
    int gridE = (ET + TB - 1) / TB;

    probe_kernel<<<1, 256>>>((const int*)ei);
    zero_counts_kernel<<<gridN, TB>>>();
    count_kernel<<<gridE, TB>>>(ei);

    // launch 4: GEMM1 (profiled slot)
    {
        dim3 g((N_NODES + 127) / 128, (HEADS * HID) / 64);
        gemm_f16_kernel<false><<<g, 256>>>(x, W1, N_NODES, HEADS * HID, D_IN);
    }

    scan_part_kernel<<<NBLK, SCAN_BLK>>>();
    scan_sums_kernel<<<1, 64>>>();
    scan_fixup_kernel<<<NBLK, SCAN_BLK>>>();
    scatter_kernel<<<gridE, TB>>>(ei);

    alpha_kernel<<<(N_NODES * HEADS + 7) / 8, 256>>>(as1, ad1, HEADS);
    aggregate_warp_kernel<HEADS, HID, true>
        <<<(N_NODES * HEADS + 7) / 8, 256>>>(b1, nullptr);

    {
        dim3 g((N_NODES + 127) / 128, HID / 64);
        gemm_f16_kernel<true><<<g, 256>>>(nullptr, W2, N_NODES, HID, HEADS * HID);
    }
    alpha_kernel<<<(N_NODES + 7) / 8, 256>>>(as2, ad2, 1);
    aggregate_warp_kernel<1, HID, false>
        <<<(N_NODES + 7) / 8, 256>>>(b2, out);
}

// round 8
// speedup vs baseline: 1.2082x; 1.2082x over previous
#include <cuda_runtime.h>
#include <cuda_fp16.h>
#include <cstdint>
#include <cstddef>

#define N_NODES 50000
#define NE      640000
#define ET      (NE + N_NODES)   // edges + self loops = 690000
#define D_IN    128
#define HID     64
#define HEADS   3
#define SLOPE   0.2f
#define EPS     1e-16f

#define SCAN_BLK 1024
#define NBLK     ((N_NODES + SCAN_BLK - 1) / SCAN_BLK)   // 49

// ---------------- scratch (no allocations; referenced ONLY from device code) ----------------
__device__ __half g_xwh[(size_t)N_NODES * HEADS * HID]; // fp16 features (xw1, then xw2)
__device__ __half g_h1h[(size_t)N_NODES * HEADS * HID]; // layer-1 output (fp16, GEMM2 input)
__device__ float  g_asrc[N_NODES * HEADS];
__device__ float  g_adst[N_NODES * HEADS];
__device__ int    g_counts[N_NODES];
__device__ int    g_offsets[N_NODES + 1];
__device__ int    g_cursor[N_NODES];
__device__ int    g_csr_src[ET];
__device__ int    g_blocksums[NBLK];
__device__ int    g_blockbase[NBLK];
__device__ int    g_is64;

// ---------------- edge-index dtype probe ----------------
__global__ void probe_kernel(const int* __restrict__ ei32) {
    __shared__ int s_or[256];
    int tid = threadIdx.x;
    int acc = 0;
    for (int i = tid; i < 2048; i += 256) acc |= ei32[2 * i + 1];
    s_or[tid] = acc;
    __syncthreads();
    for (int s = 128; s > 0; s >>= 1) {
        if (tid < s) s_or[tid] |= s_or[tid + s];
        __syncthreads();
    }
    if (tid == 0) g_is64 = (s_or[0] == 0) ? 1 : 0;
}

__device__ __forceinline__ int edge_at(const void* ei, long long idx) {
    if (g_is64) return (int)((const long long*)ei)[idx];
    return ((const int*)ei)[idx];
}

// ---------------- CSR build ----------------
__global__ void zero_counts_kernel() {
    int i = blockIdx.x * blockDim.x + threadIdx.x;
    if (i < N_NODES) g_counts[i] = 0;
}

__global__ void count_kernel(const void* __restrict__ ei) {
    int e = blockIdx.x * blockDim.x + threadIdx.x;
    if (e >= ET) return;
    int dst = (e < NE) ? edge_at(ei, (long long)NE + e) : (e - NE);
    atomicAdd(&g_counts[dst], 1);
}

__global__ void scan_part_kernel() {
    __shared__ int warp_sums[32];
    int tid = threadIdx.x, lane = tid & 31, wid = tid >> 5;
    int idx = blockIdx.x * SCAN_BLK + tid;
    int v = (idx < N_NODES) ? g_counts[idx] : 0;
    int x = v;
    #pragma unroll
    for (int o = 1; o < 32; o <<= 1) {
        int y = __shfl_up_sync(0xffffffffu, x, o);
        if (lane >= o) x += y;
    }
    if (lane == 31) warp_sums[wid] = x;
    __syncthreads();
    if (wid == 0) {
        int w = warp_sums[lane];
        #pragma unroll
        for (int o = 1; o < 32; o <<= 1) {
            int y = __shfl_up_sync(0xffffffffu, w, o);
            if (lane >= o) w += y;
        }
        warp_sums[lane] = w;
    }
    __syncthreads();
    int warp_off = (wid > 0) ? warp_sums[wid - 1] : 0;
    int incl = x + warp_off;
    if (idx < N_NODES) g_offsets[idx] = incl - v;
    if (tid == SCAN_BLK - 1) g_blocksums[blockIdx.x] = incl;
}

__global__ void scan_sums_kernel() {
    int tid = threadIdx.x;
    __shared__ int s[NBLK];
    if (tid < NBLK) s[tid] = g_blocksums[tid];
    __syncthreads();
    if (tid == 0) {
        int run = 0;
        for (int i = 0; i < NBLK; i++) { g_blockbase[i] = run; run += s[i]; }
        g_offsets[N_NODES] = run;
    }
}

__global__ void scan_fixup_kernel() {
    int idx = blockIdx.x * SCAN_BLK + threadIdx.x;
    if (idx < N_NODES) {
        int v = g_offsets[idx] + g_blockbase[blockIdx.x];
        g_offsets[idx] = v;
        g_cursor[idx] = v;
    }
}

__global__ void scatter_kernel(const void* __restrict__ ei) {
    int e = blockIdx.x * blockDim.x + threadIdx.x;
    if (e >= ET) return;
    int src, dst;
    if (e < NE) {
        src = edge_at(ei, e);
        dst = edge_at(ei, (long long)NE + e);
    } else {
        src = e - NE; dst = e - NE;
    }
    int pos = atomicAdd(&g_cursor[dst], 1);
    g_csr_src[pos] = src;
}

// ---------------- fp16 tensor-core GEMM -> fp16 feature buffer ----------------
#define ASTR 40   // smem row stride in halves: (20g+t) mod 32 distinct -> conflict-free

__device__ __forceinline__ void mma_f16(float* d, const uint32_t* a, const uint32_t* b) {
    asm volatile(
        "mma.sync.aligned.m16n8k16.row.col.f32.f16.f16.f32 "
        "{%0,%1,%2,%3}, {%4,%5,%6,%7}, {%8,%9}, {%0,%1,%2,%3};\n"
        : "+f"(d[0]), "+f"(d[1]), "+f"(d[2]), "+f"(d[3])
        : "r"(a[0]), "r"(a[1]), "r"(a[2]), "r"(a[3]), "r"(b[0]), "r"(b[1]));
}

template <bool A_HALF>
__global__ __launch_bounds__(256)
void gemm_f16_kernel(const float* __restrict__ Af, const float* __restrict__ B,
                     int M, int N, int K) {
    __shared__ __half As[128 * ASTR];
    __shared__ __half Bs[64 * ASTR];
    int tid = threadIdx.x;
    int lane = tid & 31, wid = tid >> 5;
    int warp_m = wid & 3, warp_n = wid >> 2;
    int m0 = blockIdx.x * 128, n0 = blockIdx.y * 64;
    int g = lane >> 2, t = lane & 3;

    float acc[2][4][4];
    #pragma unroll
    for (int i = 0; i < 2; i++)
        #pragma unroll
        for (int j = 0; j < 4; j++)
            #pragma unroll
            for (int q = 0; q < 4; q++) acc[i][j][q] = 0.f;

    const __half* Ah = A_HALF ? (const __half*)g_h1h : nullptr;

    for (int k0 = 0; k0 < K; k0 += 32) {
        #pragma unroll
        for (int s = tid; s < 1024; s += 256) {
            int r = s >> 3, c = (s & 7) * 4;
            __half2 h01, h23;
            if (m0 + r < M) {
                if (A_HALF) {
                    const __half* ap = Ah + (size_t)(m0 + r) * K + k0 + c;
                    h01 = *(const __half2*)ap;
                    h23 = *(const __half2*)(ap + 2);
                } else {
                    float4 v = *(const float4*)(Af + (size_t)(m0 + r) * K + k0 + c);
                    h01 = __floats2half2_rn(v.x, v.y);
                    h23 = __floats2half2_rn(v.z, v.w);
                }
            } else {
                h01 = __floats2half2_rn(0.f, 0.f);
                h23 = h01;
            }
            *(__half2*)&As[r * ASTR + c] = h01;
            *(__half2*)&As[r * ASTR + c + 2] = h23;
        }
        #pragma unroll
        for (int s = tid; s < 512; s += 256) {
            int kk = s >> 4, n = (s & 15) * 4;
            float4 v = *(const float4*)(B + (size_t)(k0 + kk) * N + n0 + n);
            Bs[(n + 0) * ASTR + kk] = __float2half_rn(v.x);
            Bs[(n + 1) * ASTR + kk] = __float2half_rn(v.y);
            Bs[(n + 2) * ASTR + kk] = __float2half_rn(v.z);
            Bs[(n + 3) * ASTR + kk] = __float2half_rn(v.w);
        }
        __syncthreads();
        #pragma unroll
        for (int k16 = 0; k16 < 32; k16 += 16) {
            uint32_t af[2][4];
            #pragma unroll
            for (int am = 0; am < 2; am++) {
                int r0 = warp_m * 32 + am * 16 + g;
                af[am][0] = *(const uint32_t*)&As[(r0)     * ASTR + k16 + 2 * t];
                af[am][1] = *(const uint32_t*)&As[(r0 + 8) * ASTR + k16 + 2 * t];
                af[am][2] = *(const uint32_t*)&As[(r0)     * ASTR + k16 + 2 * t + 8];
                af[am][3] = *(const uint32_t*)&As[(r0 + 8) * ASTR + k16 + 2 * t + 8];
            }
            uint32_t bf[4][2];
            #pragma unroll
            for (int an = 0; an < 4; an++) {
                int nn = warp_n * 32 + an * 8 + g;
                bf[an][0] = *(const uint32_t*)&Bs[nn * ASTR + k16 + 2 * t];
                bf[an][1] = *(const uint32_t*)&Bs[nn * ASTR + k16 + 2 * t + 8];
            }
            #pragma unroll
            for (int am = 0; am < 2; am++)
                #pragma unroll
                for (int an = 0; an < 4; an++)
                    mma_f16(acc[am][an], af[am], bf[an]);
        }
        __syncthreads();
    }

    #pragma unroll
    for (int am = 0; am < 2; am++) {
        int r0 = m0 + warp_m * 32 + am * 16 + g;
        #pragma unroll
        for (int an = 0; an < 4; an++) {
            int cn = n0 + warp_n * 32 + an * 8 + 2 * t;
            if (r0 < M)
                *(__half2*)&g_xwh[(size_t)r0 * N + cn] =
                    __floats2half2_rn(acc[am][an][0], acc[am][an][1]);
            if (r0 + 8 < M)
                *(__half2*)&g_xwh[(size_t)(r0 + 8) * N + cn] =
                    __floats2half2_rn(acc[am][an][2], acc[am][an][3]);
        }
    }
}

// ---------------- per-node attention coefficients (reads fp16 features) ----------------
__global__ void alpha_kernel(const float* __restrict__ a_src,
                             const float* __restrict__ a_dst, int H) {
    int warp = (blockIdx.x * blockDim.x + threadIdx.x) >> 5;
    int lane = threadIdx.x & 31;
    if (warp >= N_NODES * H) return;
    int n = warp / H, h = warp % H;
    const __half* row = g_xwh + (size_t)n * H * HID + h * HID;
    const float* asv = a_src + h * HID;
    const float* adv = a_dst + h * HID;
    float r1 = __half2float(row[lane]);
    float r2 = __half2float(row[lane + 32]);
    float s1 = r1 * asv[lane] + r2 * asv[lane + 32];
    float s2 = r1 * adv[lane] + r2 * adv[lane + 32];
    #pragma unroll
    for (int o = 16; o > 0; o >>= 1) {
        s1 += __shfl_xor_sync(0xffffffffu, s1, o);
        s2 += __shfl_xor_sync(0xffffffffu, s2, o);
    }
    if (lane == 0) {
        g_asrc[n * H + h] = s1;
        g_adst[n * H + h] = s2;
    }
}

// ---------------- layer-1 fused aggregate: 3 heads per warp, one warp per node ----------------
// out (g_h1h, fp16): relu(sum_e ex_e[h]*xw[src_e,h]/denom[h] + bias).
// Per edge: 1 src load, 1 asrc[3] load, 4 shfls, 6 feature loads (2-edge unroll).
__global__ __launch_bounds__(256)
void aggregate3_kernel(const float* __restrict__ bias) {
    int n = (blockIdx.x * blockDim.x + threadIdx.x) >> 5;
    int lane = threadIdx.x & 31;
    if (n >= N_NODES) return;
    int beg = g_offsets[n], end = g_offsets[n + 1];
    float ad0 = g_adst[n * 3 + 0];
    float ad1 = g_adst[n * 3 + 1];
    float ad2 = g_adst[n * 3 + 2];

    float2 a0 = make_float2(0.f, 0.f), a1 = a0, a2 = a0;
    float d0 = 0.f, d1 = 0.f, d2 = 0.f;
    const __half* xwh = g_xwh;

    for (int base = beg; base < end; base += 32) {
        int j = base + lane;
        bool valid = j < end;
        int s = valid ? g_csr_src[j] : 0;
        float e0 = 0.f, e1 = 0.f, e2 = 0.f;
        if (valid) {
            const float* ap = &g_asrc[s * 3];
            float v0 = ap[0] + ad0, v1 = ap[1] + ad1, v2 = ap[2] + ad2;
            v0 = (v0 > 0.f) ? v0 : SLOPE * v0;
            v1 = (v1 > 0.f) ? v1 : SLOPE * v1;
            v2 = (v2 > 0.f) ? v2 : SLOPE * v2;
            e0 = __expf(v0); e1 = __expf(v1); e2 = __expf(v2);
        }
        d0 += e0; d1 += e1; d2 += e2;
        int ne = min(32, end - base);
        int jj = 0;
        for (; jj + 2 <= ne; jj += 2) {
            int   sA  = __shfl_sync(0xffffffffu, s,  jj);
            int   sB  = __shfl_sync(0xffffffffu, s,  jj + 1);
            float eA0 = __shfl_sync(0xffffffffu, e0, jj);
            float eA1 = __shfl_sync(0xffffffffu, e1, jj);
            float eA2 = __shfl_sync(0xffffffffu, e2, jj);
            float eB0 = __shfl_sync(0xffffffffu, e0, jj + 1);
            float eB1 = __shfl_sync(0xffffffffu, e1, jj + 1);
            float eB2 = __shfl_sync(0xffffffffu, e2, jj + 1);
            const __half* rA = &xwh[(size_t)sA * 192 + 2 * lane];
            const __half* rB = &xwh[(size_t)sB * 192 + 2 * lane];
            float2 fA0 = __half22float2(*(const __half2*)(rA));
            float2 fA1 = __half22float2(*(const __half2*)(rA + 64));
            float2 fA2 = __half22float2(*(const __half2*)(rA + 128));
            float2 fB0 = __half22float2(*(const __half2*)(rB));
            float2 fB1 = __half22float2(*(const __half2*)(rB + 64));
            float2 fB2 = __half22float2(*(const __half2*)(rB + 128));
            a0.x += eA0 * fA0.x + eB0 * fB0.x;  a0.y += eA0 * fA0.y + eB0 * fB0.y;
            a1.x += eA1 * fA1.x + eB1 * fB1.x;  a1.y += eA1 * fA1.y + eB1 * fB1.y;
            a2.x += eA2 * fA2.x + eB2 * fB2.x;  a2.y += eA2 * fA2.y + eB2 * fB2.y;
        }
        if (jj < ne) {
            int   sA  = __shfl_sync(0xffffffffu, s,  jj);
            float eA0 = __shfl_sync(0xffffffffu, e0, jj);
            float eA1 = __shfl_sync(0xffffffffu, e1, jj);
            float eA2 = __shfl_sync(0xffffffffu, e2, jj);
            const __half* rA = &xwh[(size_t)sA * 192 + 2 * lane];
            float2 fA0 = __half22float2(*(const __half2*)(rA));
            float2 fA1 = __half22float2(*(const __half2*)(rA + 64));
            float2 fA2 = __half22float2(*(const __half2*)(rA + 128));
            a0.x += eA0 * fA0.x;  a0.y += eA0 * fA0.y;
            a1.x += eA1 * fA1.x;  a1.y += eA1 * fA1.y;
            a2.x += eA2 * fA2.x;  a2.y += eA2 * fA2.y;
        }
    }
    #pragma unroll
    for (int o = 16; o > 0; o >>= 1) {
        d0 += __shfl_xor_sync(0xffffffffu, d0, o);
        d1 += __shfl_xor_sync(0xffffffffu, d1, o);
        d2 += __shfl_xor_sync(0xffffffffu, d2, o);
    }
    float i0 = 1.f / (d0 + EPS), i1 = 1.f / (d1 + EPS), i2 = 1.f / (d2 + EPS);
    int c = 2 * lane;
    __half* orow = &g_h1h[(size_t)n * 192];
    *(__half2*)&orow[c] = __floats2half2_rn(
        fmaxf(a0.x * i0 + bias[c], 0.f),       fmaxf(a0.y * i0 + bias[c + 1], 0.f));
    *(__half2*)&orow[c + 64] = __floats2half2_rn(
        fmaxf(a1.x * i1 + bias[c + 64], 0.f),  fmaxf(a1.y * i1 + bias[c + 65], 0.f));
    *(__half2*)&orow[c + 128] = __floats2half2_rn(
        fmaxf(a2.x * i2 + bias[c + 128], 0.f), fmaxf(a2.y * i2 + bias[c + 129], 0.f));
}

// ---------------- layer-2 aggregate: H=1, one warp per node, fp32 out ----------------
__global__ __launch_bounds__(256)
void aggregate1_kernel(const float* __restrict__ bias, float* __restrict__ out) {
    int n = (blockIdx.x * blockDim.x + threadIdx.x) >> 5;
    int lane = threadIdx.x & 31;
    if (n >= N_NODES) return;
    int beg = g_offsets[n], end = g_offsets[n + 1];
    float adst_n = g_adst[n];

    float2 acc = make_float2(0.f, 0.f);
    float denom = 0.f;
    const __half* xwh = g_xwh;

    for (int base = beg; base < end; base += 32) {
        int j = base + lane;
        bool valid = j < end;
        int s = valid ? g_csr_src[j] : 0;
        float e = 0.f;
        if (valid) {
            float v = g_asrc[s] + adst_n;
            v = (v > 0.f) ? v : SLOPE * v;
            e = __expf(v);
        }
        denom += e;
        int ne = min(32, end - base);
        int jj = 0;
        for (; jj + 4 <= ne; jj += 4) {
            float ev[4]; int sv[4];
            #pragma unroll
            for (int q = 0; q < 4; q++) {
                ev[q] = __shfl_sync(0xffffffffu, e, jj + q);
                sv[q] = __shfl_sync(0xffffffffu, s, jj + q);
            }
            float2 f[4];
            #pragma unroll
            for (int q = 0; q < 4; q++)
                f[q] = __half22float2(*(const __half2*)&xwh[(size_t)sv[q] * 64 + 2 * lane]);
            #pragma unroll
            for (int q = 0; q < 4; q++) {
                acc.x += ev[q] * f[q].x;
                acc.y += ev[q] * f[q].y;
            }
        }
        for (; jj < ne; jj++) {
            float ee = __shfl_sync(0xffffffffu, e, jj);
            int   ss = __shfl_sync(0xffffffffu, s, jj);
            float2 f = __half22float2(*(const __half2*)&xwh[(size_t)ss * 64 + 2 * lane]);
            acc.x += ee * f.x; acc.y += ee * f.y;
        }
    }
    #pragma unroll
    for (int o = 16; o > 0; o >>= 1)
        denom += __shfl_xor_sync(0xffffffffu, denom, o);
    float inv = 1.f / (denom + EPS);
    int c = 2 * lane;
    *(float2*)&out[(size_t)n * 64 + c] = make_float2(
        fmaxf(acc.x * inv + bias[c], 0.f), fmaxf(acc.y * inv + bias[c + 1], 0.f));
}

// ---------------- launch ----------------
extern "C" void kernel_launch(void* const* d_in, const int* in_sizes, int n_in,
                              void* d_out, int out_size) {
    const float* x   = (const float*)d_in[0];
    const void*  ei  = d_in[1];
    const float* W1  = (const float*)d_in[2];
    const float* as1 = (const float*)d_in[3];
    const float* ad1 = (const float*)d_in[4];
    const float* b1  = (const float*)d_in[5];
    const float* W2  = (const float*)d_in[6];
    const float* as2 = (const float*)d_in[7];
    const float* ad2 = (const float*)d_in[8];
    const float* b2  = (const float*)d_in[9];
    float*       out = (float*)d_out;

    const int TB = 256;
    int gridN = (N_NODES + TB - 1) / TB;
    int gridE = (ET + TB - 1) / TB;

    probe_kernel<<<1, 256>>>((const int*)ei);
    zero_counts_kernel<<<gridN, TB>>>();
    count_kernel<<<gridE, TB>>>(ei);

    {
        dim3 g((N_NODES + 127) / 128, (HEADS * HID) / 64);
        gemm_f16_kernel<false><<<g, 256>>>(x, W1, N_NODES, HEADS * HID, D_IN);
    }

    scan_part_kernel<<<NBLK, SCAN_BLK>>>();
    scan_sums_kernel<<<1, 64>>>();
    scan_fixup_kernel<<<NBLK, SCAN_BLK>>>();
    scatter_kernel<<<gridE, TB>>>(ei);

    alpha_kernel<<<(N_NODES * HEADS + 7) / 8, 256>>>(as1, ad1, HEADS);
    aggregate3_kernel<<<(N_NODES + 7) / 8, 256>>>(b1);

    {
        dim3 g((N_NODES + 127) / 128, HID / 64);
        gemm_f16_kernel<true><<<g, 256>>>(nullptr, W2, N_NODES, HID, HEADS * HID);
    }
    alpha_kernel<<<(N_NODES + 7) / 8, 256>>>(as2, ad2, 1);
    aggregate1_kernel<<<(N_NODES + 7) / 8, 256>>>(b2, out);
}

// round 10
// speedup vs baseline: 1.2504x; 1.0350x over previous
#include <cuda_runtime.h>
#include <cuda_fp16.h>
#include <cstdint>
#include <cstddef>

#define N_NODES 50000
#define M_PAD   50048    // 391 * 128, so GEMM A-loads need no row guards
#define NE      640000
#define ET      (NE + N_NODES)
#define D_IN    128
#define HID     64
#define HEADS   3
#define SLOPE   0.2f
#define EPS     1e-16f

#define SCAN_BLK 1024
#define NBLK     ((N_NODES + SCAN_BLK - 1) / SCAN_BLK)   // 49
#define ASTR     40      // smem row stride in halves (80 B)

// ---------------- scratch (referenced ONLY from device code) ----------------
__device__ __half g_xh[(size_t)M_PAD * D_IN];            // fp16 input features
__device__ __half g_w1t[(HEADS * HID) * D_IN];           // W1^T [192][128] fp16
__device__ __half g_w2t[HID * (HEADS * HID)];            // W2^T [64][192] fp16
__device__ __half g_xwh[(size_t)N_NODES * HEADS * HID];  // GEMM output (xw1, then xw2)
__device__ __half g_h1h[(size_t)M_PAD * HEADS * HID];    // layer-1 out (fp16, GEMM2 A)
__device__ float  g_asrc[N_NODES * HEADS];
__device__ float  g_adst[N_NODES * HEADS];
__device__ int    g_counts[N_NODES];
__device__ int    g_offsets[N_NODES + 1];
__device__ int    g_cursor[N_NODES];
__device__ int    g_csr_src[ET];
__device__ int    g_blocksums[NBLK];
__device__ int    g_blockbase[NBLK];
__device__ int    g_is64;

// ---------------- small helpers ----------------
__device__ __forceinline__ uint32_t smem_u32(const void* p) {
    return (uint32_t)__cvta_generic_to_shared(p);
}
__device__ __forceinline__ void cp16(uint32_t dst, const void* src) {
    asm volatile("cp.async.cg.shared.global [%0], [%1], 16;\n" :: "r"(dst), "l"(src));
}
__device__ __forceinline__ void cp_commit() {
    asm volatile("cp.async.commit_group;\n");
}
template <int N> __device__ __forceinline__ void cp_wait() {
    asm volatile("cp.async.wait_group %0;\n" :: "n"(N));
}
__device__ __forceinline__ void ldsm4(uint32_t& r0, uint32_t& r1, uint32_t& r2,
                                      uint32_t& r3, uint32_t addr) {
    asm volatile("ldmatrix.sync.aligned.m8n8.x4.shared.b16 {%0,%1,%2,%3}, [%4];\n"
                 : "=r"(r0), "=r"(r1), "=r"(r2), "=r"(r3) : "r"(addr));
}
__device__ __forceinline__ void mma_f16(float* d, const uint32_t* a, const uint32_t* b) {
    asm volatile(
        "mma.sync.aligned.m16n8k16.row.col.f32.f16.f16.f32 "
        "{%0,%1,%2,%3}, {%4,%5,%6,%7}, {%8,%9}, {%0,%1,%2,%3};\n"
        : "+f"(d[0]), "+f"(d[1]), "+f"(d[2]), "+f"(d[3])
        : "r"(a[0]), "r"(a[1]), "r"(a[2]), "r"(a[3]), "r"(b[0]), "r"(b[1]));
}

// ---------------- edge-index dtype probe ----------------
__global__ void probe_kernel(const int* __restrict__ ei32) {
    __shared__ int s_or[256];
    int tid = threadIdx.x;
    int acc = 0;
    for (int i = tid; i < 2048; i += 256) acc |= ei32[2 * i + 1];
    s_or[tid] = acc;
    __syncthreads();
    for (int s = 128; s > 0; s >>= 1) {
        if (tid < s) s_or[tid] |= s_or[tid + s];
        __syncthreads();
    }
    if (tid == 0) g_is64 = (s_or[0] == 0) ? 1 : 0;
}

__device__ __forceinline__ int edge_at(const void* ei, long long idx) {
    if (g_is64) return (int)((const long long*)ei)[idx];
    return ((const int*)ei)[idx];
}

// ---------------- input conversion ----------------
__global__ void convert_x_kernel(const float* __restrict__ x) {
    int i = blockIdx.x * blockDim.x + threadIdx.x;   // float4 index
    if (i >= N_NODES * D_IN / 4) return;
    float4 v = *(const float4*)(x + 4 * (size_t)i);
    __half2* d = (__half2*)&g_xh[4 * (size_t)i];
    d[0] = __floats2half2_rn(v.x, v.y);
    d[1] = __floats2half2_rn(v.z, v.w);
}

__global__ void convert_w_kernel(const float* __restrict__ W1,
                                 const float* __restrict__ W2) {
    int i = blockIdx.x * blockDim.x + threadIdx.x;
    if (i < (HEADS * HID) * D_IN) {
        int n = i / D_IN, k = i % D_IN;
        g_w1t[i] = __float2half_rn(W1[(size_t)k * (HEADS * HID) + n]);
    }
    if (i < HID * (HEADS * HID)) {
        int n = i / (HEADS * HID), k = i % (HEADS * HID);
        g_w2t[i] = __float2half_rn(W2[(size_t)k * HID + n]);
    }
}

// ---------------- CSR build ----------------
__global__ void zero_counts_kernel() {
    int i = blockIdx.x * blockDim.x + threadIdx.x;
    if (i < N_NODES) g_counts[i] = 0;
}

__global__ void count_kernel(const void* __restrict__ ei) {
    int e = blockIdx.x * blockDim.x + threadIdx.x;
    if (e >= ET) return;
    int dst = (e < NE) ? edge_at(ei, (long long)NE + e) : (e - NE);
    atomicAdd(&g_counts[dst], 1);
}

__global__ void scan_part_kernel() {
    __shared__ int warp_sums[32];
    int tid = threadIdx.x, lane = tid & 31, wid = tid >> 5;
    int idx = blockIdx.x * SCAN_BLK + tid;
    int v = (idx < N_NODES) ? g_counts[idx] : 0;
    int x = v;
    #pragma unroll
    for (int o = 1; o < 32; o <<= 1) {
        int y = __shfl_up_sync(0xffffffffu, x, o);
        if (lane >= o) x += y;
    }
    if (lane == 31) warp_sums[wid] = x;
    __syncthreads();
    if (wid == 0) {
        int w = warp_sums[lane];
        #pragma unroll
        for (int o = 1; o < 32; o <<= 1) {
            int y = __shfl_up_sync(0xffffffffu, w, o);
            if (lane >= o) w += y;
        }
        warp_sums[lane] = w;
    }
    __syncthreads();
    int warp_off = (wid > 0) ? warp_sums[wid - 1] : 0;
    int incl = x + warp_off;
    if (idx < N_NODES) g_offsets[idx] = incl - v;
    if (tid == SCAN_BLK - 1) g_blocksums[blockIdx.x] = incl;
}

__global__ void scan_sums_kernel() {
    int tid = threadIdx.x;
    __shared__ int s[NBLK];
    if (tid < NBLK) s[tid] = g_blocksums[tid];
    __syncthreads();
    if (tid == 0) {
        int run = 0;
        for (int i = 0; i < NBLK; i++) { g_blockbase[i] = run; run += s[i]; }
        g_offsets[N_NODES] = run;
    }
}

__global__ void scan_fixup_kernel() {
    int idx = blockIdx.x * SCAN_BLK + threadIdx.x;
    if (idx < N_NODES) {
        int v = g_offsets[idx] + g_blockbase[blockIdx.x];
        g_offsets[idx] = v;
        g_cursor[idx] = v;
    }
}

__global__ void scatter_kernel(const void* __restrict__ ei) {
    int e = blockIdx.x * blockDim.x + threadIdx.x;
    if (e >= ET) return;
    int src, dst;
    if (e < NE) {
        src = edge_at(ei, e);
        dst = edge_at(ei, (long long)NE + e);
    } else {
        src = e - NE; dst = e - NE;
    }
    int pos = atomicAdd(&g_cursor[dst], 1);
    g_csr_src[pos] = src;
}

// ---------------- fp16 GEMM with cp.async + ldmatrix ----------------
// g_xwh[M,N] = half(A @ Bt^T), A fp16 [M_PAD][K] row-major, Bt fp16 [N][K].
// LAYER 1: A=g_xh, B=g_w1t, N=192, K=128; LAYER 2: A=g_h1h, B=g_w2t, N=64, K=192.
// BM=128, BN=64, BK=32, 2-stage cp.async pipeline, 8 warps 4(m)x2(n).
template <int LAYER>
__global__ __launch_bounds__(256)
void gemm_h_kernel() {
    constexpr int N = (LAYER == 1) ? HEADS * HID : HID;
    constexpr int K = (LAYER == 1) ? D_IN : HEADS * HID;
    constexpr int KT = K / 32;
    const __half* A  = (LAYER == 1) ? g_xh : g_h1h;
    const __half* Bt = (LAYER == 1) ? g_w1t : g_w2t;
    constexpr int M = N_NODES;

    __shared__ __half As[2][128 * ASTR];
    __shared__ __half Bs[2][64 * ASTR];
    constexpr uint32_t stA = 128 * ASTR * 2;   // bytes per A stage
    constexpr uint32_t stB = 64 * ASTR * 2;

    int tid = threadIdx.x;
    int lane = tid & 31, wid = tid >> 5;
    int warp_m = wid & 3, warp_n = wid >> 2;
    int m0 = blockIdx.x * 128, n0 = blockIdx.y * 64;
    int g = lane >> 2, t = lane & 3;

    uint32_t as0 = smem_u32(&As[0][0]);
    uint32_t bs0 = smem_u32(&Bs[0][0]);

    // ldmatrix per-lane base addresses (stage 0, k16=0)
    uint32_t aaddr[2], baddr[2];
    #pragma unroll
    for (int am = 0; am < 2; am++)
        aaddr[am] = as0 + 2 * ((warp_m * 32 + am * 16 + ((lane >> 3) & 1) * 8 + (lane & 7)) * ASTR
                               + (lane >> 4) * 8);
    #pragma unroll
    for (int p = 0; p < 2; p++)
        baddr[p] = bs0 + 2 * ((warp_n * 32 + p * 16 + (lane >> 4) * 8 + (lane & 7)) * ASTR
                              + ((lane >> 3) & 1) * 8);

    // staging coordinates
    int ar0 = tid >> 2;               // A rows for chunk 0 (0..63) and +64
    int ac  = (tid & 3) * 8;
    int br  = tid >> 2;               // B row 0..63
    const __half* a_src0 = A + (size_t)(m0 + ar0) * K + ac;
    const __half* a_src1 = A + (size_t)(m0 + ar0 + 64) * K + ac;
    const __half* b_src  = Bt + (size_t)(n0 + br) * K + ac;
    uint32_t a_dst0 = as0 + 2 * (ar0 * ASTR + ac);
    uint32_t a_dst1 = as0 + 2 * ((ar0 + 64) * ASTR + ac);
    uint32_t b_dst  = bs0 + 2 * (br * ASTR + ac);

    float acc[2][4][4];
    #pragma unroll
    for (int i = 0; i < 2; i++)
        #pragma unroll
        for (int j = 0; j < 4; j++)
            #pragma unroll
            for (int q = 0; q < 4; q++) acc[i][j][q] = 0.f;

    // prefetch stage 0
    cp16(a_dst0, a_src0);
    cp16(a_dst1, a_src1);
    cp16(b_dst, b_src);
    cp_commit();

    #pragma unroll
    for (int kt = 0; kt < KT; kt++) {
        int buf = kt & 1;
        if (kt + 1 < KT) {
            int nb = (kt + 1) & 1;
            int ko = (kt + 1) * 32;
            cp16(a_dst0 + nb * stA, a_src0 + ko);
            cp16(a_dst1 + nb * stA, a_src1 + ko);
            cp16(b_dst + nb * stB, b_src + ko);
            cp_commit();
            cp_wait<1>();
        } else {
            cp_wait<0>();
        }
        __syncthreads();

        uint32_t aoff = buf * stA, boff = buf * stB;
        #pragma unroll
        for (int k16 = 0; k16 < 32; k16 += 16) {
            uint32_t af[2][4], bp[2][4];
            #pragma unroll
            for (int am = 0; am < 2; am++)
                ldsm4(af[am][0], af[am][1], af[am][2], af[am][3],
                      aaddr[am] + aoff + 2 * k16);
            #pragma unroll
            for (int p = 0; p < 2; p++)
                ldsm4(bp[p][0], bp[p][1], bp[p][2], bp[p][3],
                      baddr[p] + boff + 2 * k16);
            #pragma unroll
            for (int am = 0; am < 2; am++)
                #pragma unroll
                for (int an = 0; an < 4; an++) {
                    const uint32_t bfr[2] = {bp[an >> 1][(an & 1) * 2],
                                             bp[an >> 1][(an & 1) * 2 + 1]};
                    mma_f16(acc[am][an], af[am], bfr);
                }
        }
        __syncthreads();
    }

    #pragma unroll
    for (int am = 0; am < 2; am++) {
        int r0 = m0 + warp_m * 32 + am * 16 + g;
        #pragma unroll
        for (int an = 0; an < 4; an++) {
            int cn = n0 + warp_n * 32 + an * 8 + 2 * t;
            if (r0 < M)
                *(__half2*)&g_xwh[(size_t)r0 * N + cn] =
                    __floats2half2_rn(acc[am][an][0], acc[am][an][1]);
            if (r0 + 8 < M)
                *(__half2*)&g_xwh[(size_t)(r0 + 8) * N + cn] =
                    __floats2half2_rn(acc[am][an][2], acc[am][an][3]);
        }
    }
}

// ---------------- per-node attention coefficients ----------------
__global__ void alpha_kernel(const float* __restrict__ a_src,
                             const float* __restrict__ a_dst, int H) {
    int warp = (blockIdx.x * blockDim.x + threadIdx.x) >> 5;
    int lane = threadIdx.x & 31;
    if (warp >= N_NODES * H) return;
    int n = warp / H, h = warp % H;
    const __half* row = g_xwh + (size_t)n * H * HID + h * HID;
    const float* asv = a_src + h * HID;
    const float* adv = a_dst + h * HID;
    float r1 = __half2float(row[lane]);
    float r2 = __half2float(row[lane + 32]);
    float s1 = r1 * asv[lane] + r2 * asv[lane + 32];
    float s2 = r1 * adv[lane] + r2 * adv[lane + 32];
    #pragma unroll
    for (int o = 16; o > 0; o >>= 1) {
        s1 += __shfl_xor_sync(0xffffffffu, s1, o);
        s2 += __shfl_xor_sync(0xffffffffu, s2, o);
    }
    if (lane == 0) {
        g_asrc[n * H + h] = s1;
        g_adst[n * H + h] = s2;
    }
}

// ---------------- layer-1 aggregate: 3 heads per warp, one warp per node ----------------
__global__ __launch_bounds__(256)
void aggregate3_kernel(const float* __restrict__ bias) {
    int n = (blockIdx.x * blockDim.x + threadIdx.x) >> 5;
    int lane = threadIdx.x & 31;
    if (n >= N_NODES) return;
    int beg = g_offsets[n], end = g_offsets[n + 1];
    float ad0 = g_adst[n * 3 + 0];
    float ad1 = g_adst[n * 3 + 1];
    float ad2 = g_adst[n * 3 + 2];

    float2 a0 = make_float2(0.f, 0.f), a1 = a0, a2 = a0;
    float d0 = 0.f, d1 = 0.f, d2 = 0.f;
    const __half* xwh = g_xwh;

    for (int base = beg; base < end; base += 32) {
        int j = base + lane;
        bool valid = j < end;
        int s = valid ? g_csr_src[j] : 0;
        float e0 = 0.f, e1 = 0.f, e2 = 0.f;
        if (valid) {
            const float* ap = &g_asrc[s * 3];
            float v0 = ap[0] + ad0, v1 = ap[1] + ad1, v2 = ap[2] + ad2;
            v0 = (v0 > 0.f) ? v0 : SLOPE * v0;
            v1 = (v1 > 0.f) ? v1 : SLOPE * v1;
            v2 = (v2 > 0.f) ? v2 : SLOPE * v2;
            e0 = __expf(v0); e1 = __expf(v1); e2 = __expf(v2);
        }
        d0 += e0; d1 += e1; d2 += e2;
        int ne = min(32, end - base);
        int jj = 0;
        for (; jj + 2 <= ne; jj += 2) {
            int   sA  = __shfl_sync(0xffffffffu, s,  jj);
            int   sB  = __shfl_sync(0xffffffffu, s,  jj + 1);
            float eA0 = __shfl_sync(0xffffffffu, e0, jj);
            float eA1 = __shfl_sync(0xffffffffu, e1, jj);
            float eA2 = __shfl_sync(0xffffffffu, e2, jj);
            float eB0 = __shfl_sync(0xffffffffu, e0, jj + 1);
            float eB1 = __shfl_sync(0xffffffffu, e1, jj + 1);
            float eB2 = __shfl_sync(0xffffffffu, e2, jj + 1);
            const __half* rA = &xwh[(size_t)sA * 192 + 2 * lane];
            const __half* rB = &xwh[(size_t)sB * 192 + 2 * lane];
            float2 fA0 = __half22float2(*(const __half2*)(rA));
            float2 fA1 = __half22float2(*(const __half2*)(rA + 64));
            float2 fA2 = __half22float2(*(const __half2*)(rA + 128));
            float2 fB0 = __half22float2(*(const __half2*)(rB));
            float2 fB1 = __half22float2(*(const __half2*)(rB + 64));
            float2 fB2 = __half22float2(*(const __half2*)(rB + 128));
            a0.x += eA0 * fA0.x + eB0 * fB0.x;  a0.y += eA0 * fA0.y + eB0 * fB0.y;
            a1.x += eA1 * fA1.x + eB1 * fB1.x;  a1.y += eA1 * fA1.y + eB1 * fB1.y;
            a2.x += eA2 * fA2.x + eB2 * fB2.x;  a2.y += eA2 * fA2.y + eB2 * fB2.y;
        }
        if (jj < ne) {
            int   sA  = __shfl_sync(0xffffffffu, s,  jj);
            float eA0 = __shfl_sync(0xffffffffu, e0, jj);
            float eA1 = __shfl_sync(0xffffffffu, e1, jj);
            float eA2 = __shfl_sync(0xffffffffu, e2, jj);
            const __half* rA = &xwh[(size_t)sA * 192 + 2 * lane];
            float2 fA0 = __half22float2(*(const __half2*)(rA));
            float2 fA1 = __half22float2(*(const __half2*)(rA + 64));
            float2 fA2 = __half22float2(*(const __half2*)(rA + 128));
            a0.x += eA0 * fA0.x;  a0.y += eA0 * fA0.y;
            a1.x += eA1 * fA1.x;  a1.y += eA1 * fA1.y;
            a2.x += eA2 * fA2.x;  a2.y += eA2 * fA2.y;
        }
    }
    #pragma unroll
    for (int o = 16; o > 0; o >>= 1) {
        d0 += __shfl_xor_sync(0xffffffffu, d0, o);
        d1 += __shfl_xor_sync(0xffffffffu, d1, o);
        d2 += __shfl_xor_sync(0xffffffffu, d2, o);
    }
    float i0 = 1.f / (d0 + EPS), i1 = 1.f / (d1 + EPS), i2 = 1.f / (d2 + EPS);
    int c = 2 * lane;
    __half* orow = &g_h1h[(size_t)n * 192];
    *(__half2*)&orow[c] = __floats2half2_rn(
        fmaxf(a0.x * i0 + bias[c], 0.f),       fmaxf(a0.y * i0 + bias[c + 1], 0.f));
    *(__half2*)&orow[c + 64] = __floats2half2_rn(
        fmaxf(a1.x * i1 + bias[c + 64], 0.f),  fmaxf(a1.y * i1 + bias[c + 65], 0.f));
    *(__half2*)&orow[c + 128] = __floats2half2_rn(
        fmaxf(a2.x * i2 + bias[c + 128], 0.f), fmaxf(a2.y * i2 + bias[c + 129], 0.f));
}

// ---------------- layer-2 aggregate: H=1, one warp per node, fp32 out ----------------
__global__ __launch_bounds__(256)
void aggregate1_kernel(const float* __restrict__ bias, float* __restrict__ out) {
    int n = (blockIdx.x * blockDim.x + threadIdx.x) >> 5;
    int lane = threadIdx.x & 31;
    if (n >= N_NODES) return;
    int beg = g_offsets[n], end = g_offsets[n + 1];
    float adst_n = g_adst[n];

    float2 acc = make_float2(0.f, 0.f);
    float denom = 0.f;
    const __half* xwh = g_xwh;

    for (int base = beg; base < end; base += 32) {
        int j = base + lane;
        bool valid = j < end;
        int s = valid ? g_csr_src[j] : 0;
        float e = 0.f;
        if (valid) {
            float v = g_asrc[s] + adst_n;
            v = (v > 0.f) ? v : SLOPE * v;
            e = __expf(v);
        }
        denom += e;
        int ne = min(32, end - base);
        int jj = 0;
        for (; jj + 4 <= ne; jj += 4) {
            float ev[4]; int sv[4];
            #pragma unroll
            for (int q = 0; q < 4; q++) {
                ev[q] = __shfl_sync(0xffffffffu, e, jj + q);
                sv[q] = __shfl_sync(0xffffffffu, s, jj + q);
            }
            float2 f[4];
            #pragma unroll
            for (int q = 0; q < 4; q++)
                f[q] = __half22float2(*(const __half2*)&xwh[(size_t)sv[q] * 64 + 2 * lane]);
            #pragma unroll
            for (int q = 0; q < 4; q++) {
                acc.x += ev[q] * f[q].x;
                acc.y += ev[q] * f[q].y;
            }
        }
        for (; jj < ne; jj++) {
            float ee = __shfl_sync(0xffffffffu, e, jj);
            int   ss = __shfl_sync(0xffffffffu, s, jj);
            float2 f = __half22float2(*(const __half2*)&xwh[(size_t)ss * 64 + 2 * lane]);
            acc.x += ee * f.x; acc.y += ee * f.y;
        }
    }
    #pragma unroll
    for (int o = 16; o > 0; o >>= 1)
        denom += __shfl_xor_sync(0xffffffffu, denom, o);
    float inv = 1.f / (denom + EPS);
    int c = 2 * lane;
    *(float2*)&out[(size_t)n * 64 + c] = make_float2(
        fmaxf(acc.x * inv + bias[c], 0.f), fmaxf(acc.y * inv + bias[c + 1], 0.f));
}

// ---------------- launch ----------------
extern "C" void kernel_launch(void* const* d_in, const int* in_sizes, int n_in,
                              void* d_out, int out_size) {
    const float* x   = (const float*)d_in[0];
    const void*  ei  = d_in[1];
    const float* W1  = (const float*)d_in[2];
    const float* as1 = (const float*)d_in[3];
    const float* ad1 = (const float*)d_in[4];
    const float* b1  = (const float*)d_in[5];
    const float* W2  = (const float*)d_in[6];
    const float* as2 = (const float*)d_in[7];
    const float* ad2 = (const float*)d_in[8];
    const float* b2  = (const float*)d_in[9];
    float*       out = (float*)d_out;

    const int TB = 256;
    int gridN = (N_NODES + TB - 1) / TB;
    int gridE = (ET + TB - 1) / TB;

    probe_kernel<<<1, 256>>>((const int*)ei);
    convert_x_kernel<<<(N_NODES * D_IN / 4 + TB - 1) / TB, TB>>>(x);
    convert_w_kernel<<<((HEADS * HID) * D_IN + TB - 1) / TB, TB>>>(W1, W2);

    // launch 4: GEMM1 (profiled slot)
    {
        dim3 g(M_PAD / 128, (HEADS * HID) / 64);
        gemm_h_kernel<1><<<g, 256>>>();
    }

    zero_counts_kernel<<<gridN, TB>>>();
    count_kernel<<<gridE, TB>>>(ei);
    scan_part_kernel<<<NBLK, SCAN_BLK>>>();
    scan_sums_kernel<<<1, 64>>>();
    scan_fixup_kernel<<<NBLK, SCAN_BLK>>>();
    scatter_kernel<<<gridE, TB>>>(ei);

    alpha_kernel<<<(N_NODES * HEADS + 7) / 8, 256>>>(as1, ad1, HEADS);
    aggregate3_kernel<<<(N_NODES + 7) / 8, 256>>>(b1);

    {
        dim3 g(M_PAD / 128, HID / 64);
        gemm_h_kernel<2><<<g, 256>>>();
    }
    alpha_kernel<<<(N_NODES + 7) / 8, 256>>>(as2, ad2, 1);
    aggregate1_kernel<<<(N_NODES + 7) / 8, 256>>>(b2, out);
}

// round 11
// speedup vs baseline: 1.3894x; 1.1111x over previous
#include <cuda_runtime.h>
#include <cuda_fp16.h>
#include <cstdint>
#include <cstddef>

#define N_NODES 50000
#define M_PAD   50048    // 391 * 128, so GEMM A-loads need no row guards
#define NE      640000
#define ET      (NE + N_NODES)
#define D_IN    128
#define HID     64
#define HEADS   3
#define SLOPE   0.2f
#define EPS     1e-16f

#define SCAN_BLK 1024
#define NBLK     ((N_NODES + SCAN_BLK - 1) / SCAN_BLK)   // 49
#define ASTR     40      // smem row stride in halves (80 B)

// prep_kernel block ranges
#define XBLK ((N_NODES * D_IN / 4 + 255) / 256)          // 6250 convert_x blocks
#define WBLK (((HEADS * HID) * D_IN + 255) / 256)        // 96 convert_w blocks
#define ZBLK ((N_NODES + 255) / 256)                     // 196 zero-count blocks
#define PREP_GRID (1 + XBLK + WBLK + ZBLK)

// ---------------- scratch (referenced ONLY from device code) ----------------
__device__ __half g_xh[(size_t)M_PAD * D_IN];            // fp16 input features
__device__ __half g_w1t[(HEADS * HID) * D_IN];           // W1^T [192][128] fp16
__device__ __half g_w2t[HID * (HEADS * HID)];            // W2^T [64][192] fp16
__device__ __half g_xwh[(size_t)N_NODES * HEADS * HID];  // GEMM output (xw1, then xw2)
__device__ __half g_h1h[(size_t)M_PAD * HEADS * HID];    // layer-1 out (fp16, GEMM2 A)
__device__ float  g_asrc[N_NODES * HEADS];
__device__ float  g_adst[N_NODES * HEADS];
__device__ int    g_counts[N_NODES];
__device__ int    g_offsets[N_NODES + 1];
__device__ int    g_cursor[N_NODES];
__device__ int    g_csr_src[ET];
__device__ int    g_blocksums[NBLK];
__device__ int    g_blockbase[NBLK];
__device__ int    g_is64;

// ---------------- small helpers ----------------
__device__ __forceinline__ uint32_t smem_u32(const void* p) {
    return (uint32_t)__cvta_generic_to_shared(p);
}
__device__ __forceinline__ void cp16(uint32_t dst, const void* src) {
    asm volatile("cp.async.cg.shared.global [%0], [%1], 16;\n" :: "r"(dst), "l"(src));
}
__device__ __forceinline__ void cp_commit() {
    asm volatile("cp.async.commit_group;\n");
}
template <int N> __device__ __forceinline__ void cp_wait() {
    asm volatile("cp.async.wait_group %0;\n" :: "n"(N));
}
__device__ __forceinline__ void ldsm4(uint32_t& r0, uint32_t& r1, uint32_t& r2,
                                      uint32_t& r3, uint32_t addr) {
    asm volatile("ldmatrix.sync.aligned.m8n8.x4.shared.b16 {%0,%1,%2,%3}, [%4];\n"
                 : "=r"(r0), "=r"(r1), "=r"(r2), "=r"(r3) : "r"(addr));
}
__device__ __forceinline__ void mma_f16(float* d, const uint32_t* a, const uint32_t* b) {
    asm volatile(
        "mma.sync.aligned.m16n8k16.row.col.f32.f16.f16.f32 "
        "{%0,%1,%2,%3}, {%4,%5,%6,%7}, {%8,%9}, {%0,%1,%2,%3};\n"
        : "+f"(d[0]), "+f"(d[1]), "+f"(d[2]), "+f"(d[3])
        : "r"(a[0]), "r"(a[1]), "r"(a[2]), "r"(a[3]), "r"(b[0]), "r"(b[1]));
}

__device__ __forceinline__ int edge_at(const void* ei, long long idx) {
    if (g_is64) return (int)((const long long*)ei)[idx];
    return ((const int*)ei)[idx];
}

// ---------------- fused prep: probe + convert x + convert W + zero counts ----------------
__global__ void prep_kernel(const int* __restrict__ ei32, const float* __restrict__ x,
                            const float* __restrict__ W1, const float* __restrict__ W2) {
    int b = blockIdx.x;
    int tid = threadIdx.x;
    if (b == 0) {
        // edge-index dtype probe: int64 (<2^31, LE) => all odd 32-bit words are 0
        __shared__ int s_or[256];
        int acc = 0;
        for (int i = tid; i < 2048; i += 256) acc |= ei32[2 * i + 1];
        s_or[tid] = acc;
        __syncthreads();
        for (int s = 128; s > 0; s >>= 1) {
            if (tid < s) s_or[tid] |= s_or[tid + s];
            __syncthreads();
        }
        if (tid == 0) g_is64 = (s_or[0] == 0) ? 1 : 0;
    } else if (b <= XBLK) {
        int i = (b - 1) * 256 + tid;                     // float4 index
        if (i < N_NODES * D_IN / 4) {
            float4 v = *(const float4*)(x + 4 * (size_t)i);
            __half2* d = (__half2*)&g_xh[4 * (size_t)i];
            d[0] = __floats2half2_rn(v.x, v.y);
            d[1] = __floats2half2_rn(v.z, v.w);
        }
    } else if (b <= XBLK + WBLK) {
        int i = (b - 1 - XBLK) * 256 + tid;
        if (i < (HEADS * HID) * D_IN) {
            int n = i / D_IN, k = i % D_IN;
            g_w1t[i] = __float2half_rn(W1[(size_t)k * (HEADS * HID) + n]);
        }
        if (i < HID * (HEADS * HID)) {
            int n = i / (HEADS * HID), k = i % (HEADS * HID);
            g_w2t[i] = __float2half_rn(W2[(size_t)k * HID + n]);
        }
    } else {
        int i = (b - 1 - XBLK - WBLK) * 256 + tid;
        if (i < N_NODES) g_counts[i] = 0;
    }
}

// ---------------- CSR build ----------------
__global__ void count_kernel(const void* __restrict__ ei) {
    int e = blockIdx.x * blockDim.x + threadIdx.x;
    if (e >= ET) return;
    int dst = (e < NE) ? edge_at(ei, (long long)NE + e) : (e - NE);
    atomicAdd(&g_counts[dst], 1);
}

__global__ void scan_part_kernel() {
    __shared__ int warp_sums[32];
    int tid = threadIdx.x, lane = tid & 31, wid = tid >> 5;
    int idx = blockIdx.x * SCAN_BLK + tid;
    int v = (idx < N_NODES) ? g_counts[idx] : 0;
    int x = v;
    #pragma unroll
    for (int o = 1; o < 32; o <<= 1) {
        int y = __shfl_up_sync(0xffffffffu, x, o);
        if (lane >= o) x += y;
    }
    if (lane == 31) warp_sums[wid] = x;
    __syncthreads();
    if (wid == 0) {
        int w = warp_sums[lane];
        #pragma unroll
        for (int o = 1; o < 32; o <<= 1) {
            int y = __shfl_up_sync(0xffffffffu, w, o);
            if (lane >= o) w += y;
        }
        warp_sums[lane] = w;
    }
    __syncthreads();
    int warp_off = (wid > 0) ? warp_sums[wid - 1] : 0;
    int incl = x + warp_off;
    if (idx < N_NODES) g_offsets[idx] = incl - v;
    if (tid == SCAN_BLK - 1) g_blocksums[blockIdx.x] = incl;
}

__global__ void scan_sums_kernel() {
    int tid = threadIdx.x;
    __shared__ int s[NBLK];
    if (tid < NBLK) s[tid] = g_blocksums[tid];
    __syncthreads();
    if (tid == 0) {
        int run = 0;
        for (int i = 0; i < NBLK; i++) { g_blockbase[i] = run; run += s[i]; }
        g_offsets[N_NODES] = run;
    }
}

__global__ void scan_fixup_kernel() {
    int idx = blockIdx.x * SCAN_BLK + threadIdx.x;
    if (idx < N_NODES) {
        int v = g_offsets[idx] + g_blockbase[blockIdx.x];
        g_offsets[idx] = v;
        g_cursor[idx] = v;
    }
}

__global__ void scatter_kernel(const void* __restrict__ ei) {
    int e = blockIdx.x * blockDim.x + threadIdx.x;
    if (e >= ET) return;
    int src, dst;
    if (e < NE) {
        src = edge_at(ei, e);
        dst = edge_at(ei, (long long)NE + e);
    } else {
        src = e - NE; dst = e - NE;
    }
    int pos = atomicAdd(&g_cursor[dst], 1);
    g_csr_src[pos] = src;
}

// ---------------- fp16 GEMM with cp.async + ldmatrix ----------------
// g_xwh[M,N] = half(A @ Bt^T), A fp16 [M_PAD][K] row-major, Bt fp16 [N][K].
// LAYER 1: A=g_xh, B=g_w1t, N=192, K=128; LAYER 2: A=g_h1h, B=g_w2t, N=64, K=192.
template <int LAYER>
__global__ __launch_bounds__(256)
void gemm_h_kernel() {
    constexpr int N = (LAYER == 1) ? HEADS * HID : HID;
    constexpr int K = (LAYER == 1) ? D_IN : HEADS * HID;
    constexpr int KT = K / 32;
    const __half* A  = (LAYER == 1) ? g_xh : g_h1h;
    const __half* Bt = (LAYER == 1) ? g_w1t : g_w2t;
    constexpr int M = N_NODES;

    __shared__ __half As[2][128 * ASTR];
    __shared__ __half Bs[2][64 * ASTR];
    constexpr uint32_t stA = 128 * ASTR * 2;
    constexpr uint32_t stB = 64 * ASTR * 2;

    int tid = threadIdx.x;
    int lane = tid & 31, wid = tid >> 5;
    int warp_m = wid & 3, warp_n = wid >> 2;
    int m0 = blockIdx.x * 128, n0 = blockIdx.y * 64;
    int g = lane >> 2, t = lane & 3;

    uint32_t as0 = smem_u32(&As[0][0]);
    uint32_t bs0 = smem_u32(&Bs[0][0]);

    uint32_t aaddr[2], baddr[2];
    #pragma unroll
    for (int am = 0; am < 2; am++)
        aaddr[am] = as0 + 2 * ((warp_m * 32 + am * 16 + ((lane >> 3) & 1) * 8 + (lane & 7)) * ASTR
                               + (lane >> 4) * 8);
    #pragma unroll
    for (int p = 0; p < 2; p++)
        baddr[p] = bs0 + 2 * ((warp_n * 32 + p * 16 + (lane >> 4) * 8 + (lane & 7)) * ASTR
                              + ((lane >> 3) & 1) * 8);

    int ar0 = tid >> 2;
    int ac  = (tid & 3) * 8;
    int br  = tid >> 2;
    const __half* a_src0 = A + (size_t)(m0 + ar0) * K + ac;
    const __half* a_src1 = A + (size_t)(m0 + ar0 + 64) * K + ac;
    const __half* b_src  = Bt + (size_t)(n0 + br) * K + ac;
    uint32_t a_dst0 = as0 + 2 * (ar0 * ASTR + ac);
    uint32_t a_dst1 = as0 + 2 * ((ar0 + 64) * ASTR + ac);
    uint32_t b_dst  = bs0 + 2 * (br * ASTR + ac);

    float acc[2][4][4];
    #pragma unroll
    for (int i = 0; i < 2; i++)
        #pragma unroll
        for (int j = 0; j < 4; j++)
            #pragma unroll
            for (int q = 0; q < 4; q++) acc[i][j][q] = 0.f;

    cp16(a_dst0, a_src0);
    cp16(a_dst1, a_src1);
    cp16(b_dst, b_src);
    cp_commit();

    #pragma unroll
    for (int kt = 0; kt < KT; kt++) {
        int buf = kt & 1;
        if (kt + 1 < KT) {
            int nb = (kt + 1) & 1;
            int ko = (kt + 1) * 32;
            cp16(a_dst0 + nb * stA, a_src0 + ko);
            cp16(a_dst1 + nb * stA, a_src1 + ko);
            cp16(b_dst + nb * stB, b_src + ko);
            cp_commit();
            cp_wait<1>();
        } else {
            cp_wait<0>();
        }
        __syncthreads();

        uint32_t aoff = buf * stA, boff = buf * stB;
        #pragma unroll
        for (int k16 = 0; k16 < 32; k16 += 16) {
            uint32_t af[2][4], bp[2][4];
            #pragma unroll
            for (int am = 0; am < 2; am++)
                ldsm4(af[am][0], af[am][1], af[am][2], af[am][3],
                      aaddr[am] + aoff + 2 * k16);
            #pragma unroll
            for (int p = 0; p < 2; p++)
                ldsm4(bp[p][0], bp[p][1], bp[p][2], bp[p][3],
                      baddr[p] + boff + 2 * k16);
            #pragma unroll
            for (int am = 0; am < 2; am++)
                #pragma unroll
                for (int an = 0; an < 4; an++) {
                    const uint32_t bfr[2] = {bp[an >> 1][(an & 1) * 2],
                                             bp[an >> 1][(an & 1) * 2 + 1]};
                    mma_f16(acc[am][an], af[am], bfr);
                }
        }
        __syncthreads();
    }

    #pragma unroll
    for (int am = 0; am < 2; am++) {
        int r0 = m0 + warp_m * 32 + am * 16 + g;
        #pragma unroll
        for (int an = 0; an < 4; an++) {
            int cn = n0 + warp_n * 32 + an * 8 + 2 * t;
            if (r0 < M)
                *(__half2*)&g_xwh[(size_t)r0 * N + cn] =
                    __floats2half2_rn(acc[am][an][0], acc[am][an][1]);
            if (r0 + 8 < M)
                *(__half2*)&g_xwh[(size_t)(r0 + 8) * N + cn] =
                    __floats2half2_rn(acc[am][an][2], acc[am][an][3]);
        }
    }
}

// ---------------- per-node attention coefficients ----------------
__global__ void alpha_kernel(const float* __restrict__ a_src,
                             const float* __restrict__ a_dst, int H) {
    int warp = (blockIdx.x * blockDim.x + threadIdx.x) >> 5;
    int lane = threadIdx.x & 31;
    if (warp >= N_NODES * H) return;
    int n = warp / H, h = warp % H;
    const __half* row = g_xwh + (size_t)n * H * HID + h * HID;
    const float* asv = a_src + h * HID;
    const float* adv = a_dst + h * HID;
    float r1 = __half2float(row[lane]);
    float r2 = __half2float(row[lane + 32]);
    float s1 = r1 * asv[lane] + r2 * asv[lane + 32];
    float s2 = r1 * adv[lane] + r2 * adv[lane + 32];
    #pragma unroll
    for (int o = 16; o > 0; o >>= 1) {
        s1 += __shfl_xor_sync(0xffffffffu, s1, o);
        s2 += __shfl_xor_sync(0xffffffffu, s2, o);
    }
    if (lane == 0) {
        g_asrc[n * H + h] = s1;
        g_adst[n * H + h] = s2;
    }
}

// ---------------- layer-1 aggregate: 3 heads per warp, one warp per node ----------------
__global__ __launch_bounds__(256)
void aggregate3_kernel(const float* __restrict__ bias) {
    int n = (blockIdx.x * blockDim.x + threadIdx.x) >> 5;
    int lane = threadIdx.x & 31;
    if (n >= N_NODES) return;
    int beg = g_offsets[n], end = g_offsets[n + 1];
    float ad0 = g_adst[n * 3 + 0];
    float ad1 = g_adst[n * 3 + 1];
    float ad2 = g_adst[n * 3 + 2];

    float2 a0 = make_float2(0.f, 0.f), a1 = a0, a2 = a0;
    float d0 = 0.f, d1 = 0.f, d2 = 0.f;
    const __half* xwh = g_xwh;

    for (int base = beg; base < end; base += 32) {
        int j = base + lane;
        bool valid = j < end;
        int s = valid ? g_csr_src[j] : 0;
        float e0 = 0.f, e1 = 0.f, e2 = 0.f;
        if (valid) {
            const float* ap = &g_asrc[s * 3];
            float v0 = ap[0] + ad0, v1 = ap[1] + ad1, v2 = ap[2] + ad2;
            v0 = (v0 > 0.f) ? v0 : SLOPE * v0;
            v1 = (v1 > 0.f) ? v1 : SLOPE * v1;
            v2 = (v2 > 0.f) ? v2 : SLOPE * v2;
            e0 = __expf(v0); e1 = __expf(v1); e2 = __expf(v2);
        }
        d0 += e0; d1 += e1; d2 += e2;
        int ne = min(32, end - base);
        int jj = 0;
        for (; jj + 2 <= ne; jj += 2) {
            int   sA  = __shfl_sync(0xffffffffu, s,  jj);
            int   sB  = __shfl_sync(0xffffffffu, s,  jj + 1);
            float eA0 = __shfl_sync(0xffffffffu, e0, jj);
            float eA1 = __shfl_sync(0xffffffffu, e1, jj);
            float eA2 = __shfl_sync(0xffffffffu, e2, jj);
            float eB0 = __shfl_sync(0xffffffffu, e0, jj + 1);
            float eB1 = __shfl_sync(0xffffffffu, e1, jj + 1);
            float eB2 = __shfl_sync(0xffffffffu, e2, jj + 1);
            const __half* rA = &xwh[(size_t)sA * 192 + 2 * lane];
            const __half* rB = &xwh[(size_t)sB * 192 + 2 * lane];
            float2 fA0 = __half22float2(*(const __half2*)(rA));
            float2 fA1 = __half22float2(*(const __half2*)(rA + 64));
            float2 fA2 = __half22float2(*(const __half2*)(rA + 128));
            float2 fB0 = __half22float2(*(const __half2*)(rB));
            float2 fB1 = __half22float2(*(const __half2*)(rB + 64));
            float2 fB2 = __half22float2(*(const __half2*)(rB + 128));
            a0.x += eA0 * fA0.x + eB0 * fB0.x;  a0.y += eA0 * fA0.y + eB0 * fB0.y;
            a1.x += eA1 * fA1.x + eB1 * fB1.x;  a1.y += eA1 * fA1.y + eB1 * fB1.y;
            a2.x += eA2 * fA2.x + eB2 * fB2.x;  a2.y += eA2 * fA2.y + eB2 * fB2.y;
        }
        if (jj < ne) {
            int   sA  = __shfl_sync(0xffffffffu, s,  jj);
            float eA0 = __shfl_sync(0xffffffffu, e0, jj);
            float eA1 = __shfl_sync(0xffffffffu, e1, jj);
            float eA2 = __shfl_sync(0xffffffffu, e2, jj);
            const __half* rA = &xwh[(size_t)sA * 192 + 2 * lane];
            float2 fA0 = __half22float2(*(const __half2*)(rA));
            float2 fA1 = __half22float2(*(const __half2*)(rA + 64));
            float2 fA2 = __half22float2(*(const __half2*)(rA + 128));
            a0.x += eA0 * fA0.x;  a0.y += eA0 * fA0.y;
            a1.x += eA1 * fA1.x;  a1.y += eA1 * fA1.y;
            a2.x += eA2 * fA2.x;  a2.y += eA2 * fA2.y;
        }
    }
    #pragma unroll
    for (int o = 16; o > 0; o >>= 1) {
        d0 += __shfl_xor_sync(0xffffffffu, d0, o);
        d1 += __shfl_xor_sync(0xffffffffu, d1, o);
        d2 += __shfl_xor_sync(0xffffffffu, d2, o);
    }
    float i0 = 1.f / (d0 + EPS), i1 = 1.f / (d1 + EPS), i2 = 1.f / (d2 + EPS);
    int c = 2 * lane;
    __half* orow = &g_h1h[(size_t)n * 192];
    *(__half2*)&orow[c] = __floats2half2_rn(
        fmaxf(a0.x * i0 + bias[c], 0.f),       fmaxf(a0.y * i0 + bias[c + 1], 0.f));
    *(__half2*)&orow[c + 64] = __floats2half2_rn(
        fmaxf(a1.x * i1 + bias[c + 64], 0.f),  fmaxf(a1.y * i1 + bias[c + 65], 0.f));
    *(__half2*)&orow[c + 128] = __floats2half2_rn(
        fmaxf(a2.x * i2 + bias[c + 128], 0.f), fmaxf(a2.y * i2 + bias[c + 129], 0.f));
}

// ---------------- layer-2 aggregate: H=1, one warp per node, fp32 out ----------------
__global__ __launch_bounds__(256)
void aggregate1_kernel(const float* __restrict__ bias, float* __restrict__ out) {
    int n = (blockIdx.x * blockDim.x + threadIdx.x) >> 5;
    int lane = threadIdx.x & 31;
    if (n >= N_NODES) return;
    int beg = g_offsets[n], end = g_offsets[n + 1];
    float adst_n = g_adst[n];

    float2 acc = make_float2(0.f, 0.f);
    float denom = 0.f;
    const __half* xwh = g_xwh;

    for (int base = beg; base < end; base += 32) {
        int j = base + lane;
        bool valid = j < end;
        int s = valid ? g_csr_src[j] : 0;
        float e = 0.f;
        if (valid) {
            float v = g_asrc[s] + adst_n;
            v = (v > 0.f) ? v : SLOPE * v;
            e = __expf(v);
        }
        denom += e;
        int ne = min(32, end - base);
        int jj = 0;
        for (; jj + 4 <= ne; jj += 4) {
            float ev[4]; int sv[4];
            #pragma unroll
            for (int q = 0; q < 4; q++) {
                ev[q] = __shfl_sync(0xffffffffu, e, jj + q);
                sv[q] = __shfl_sync(0xffffffffu, s, jj + q);
            }
            float2 f[4];
            #pragma unroll
            for (int q = 0; q < 4; q++)
                f[q] = __half22float2(*(const __half2*)&xwh[(size_t)sv[q] * 64 + 2 * lane]);
            #pragma unroll
            for (int q = 0; q < 4; q++) {
                acc.x += ev[q] * f[q].x;
                acc.y += ev[q] * f[q].y;
            }
        }
        for (; jj < ne; jj++) {
            float ee = __shfl_sync(0xffffffffu, e, jj);
            int   ss = __shfl_sync(0xffffffffu, s, jj);
            float2 f = __half22float2(*(const __half2*)&xwh[(size_t)ss * 64 + 2 * lane]);
            acc.x += ee * f.x; acc.y += ee * f.y;
        }
    }
    #pragma unroll
    for (int o = 16; o > 0; o >>= 1)
        denom += __shfl_xor_sync(0xffffffffu, denom, o);
    float inv = 1.f / (denom + EPS);
    int c = 2 * lane;
    *(float2*)&out[(size_t)n * 64 + c] = make_float2(
        fmaxf(acc.x * inv + bias[c], 0.f), fmaxf(acc.y * inv + bias[c + 1], 0.f));
}

// ---------------- launch ----------------
extern "C" void kernel_launch(void* const* d_in, const int* in_sizes, int n_in,
                              void* d_out, int out_size) {
    const float* x   = (const float*)d_in[0];
    const void*  ei  = d_in[1];
    const float* W1  = (const float*)d_in[2];
    const float* as1 = (const float*)d_in[3];
    const float* ad1 = (const float*)d_in[4];
    const float* b1  = (const float*)d_in[5];
    const float* W2  = (const float*)d_in[6];
    const float* as2 = (const float*)d_in[7];
    const float* ad2 = (const float*)d_in[8];
    const float* b2  = (const float*)d_in[9];
    float*       out = (float*)d_out;

    const int TB = 256;
    int gridE = (ET + TB - 1) / TB;

    // side stream + fork/join events (host-object creation only; no device memory).
    // kernel_launch host code runs only for the correctness call and the capture
    // call, so these are a bounded one-time resource, not a per-replay leak.
    cudaStream_t s2;
    cudaStreamCreateWithFlags(&s2, cudaStreamNonBlocking);
    cudaEvent_t evFork, evJoin;
    cudaEventCreateWithFlags(&evFork, cudaEventDisableTiming);
    cudaEventCreateWithFlags(&evJoin, cudaEventDisableTiming);

    // prep: probe + fp16 converts + zero counts (single launch)
    prep_kernel<<<PREP_GRID, 256>>>((const int*)ei, x, W1, W2);

    // fork: CSR chain on side stream (atomic/L2-bound)
    cudaEventRecord(evFork, 0);
    cudaStreamWaitEvent(s2, evFork, 0);
    count_kernel<<<gridE, TB, 0, s2>>>(ei);
    scan_part_kernel<<<NBLK, SCAN_BLK, 0, s2>>>();
    scan_sums_kernel<<<1, 64, 0, s2>>>();
    scan_fixup_kernel<<<NBLK, SCAN_BLK, 0, s2>>>();
    scatter_kernel<<<gridE, TB, 0, s2>>>(ei);
    cudaEventRecord(evJoin, s2);

    // main stream: GEMM1 + alpha1 (tensor/latency-bound) overlapped with CSR
    {
        dim3 g(M_PAD / 128, (HEADS * HID) / 64);
        gemm_h_kernel<1><<<g, 256>>>();
    }
    alpha_kernel<<<(N_NODES * HEADS + 7) / 8, 256>>>(as1, ad1, HEADS);

    // join, then the serial tail
    cudaStreamWaitEvent(0, evJoin, 0);
    aggregate3_kernel<<<(N_NODES + 7) / 8, 256>>>(b1);

    {
        dim3 g(M_PAD / 128, HID / 64);
        gemm_h_kernel<2><<<g, 256>>>();
    }
    alpha_kernel<<<(N_NODES + 7) / 8, 256>>>(as2, ad2, 1);
    aggregate1_kernel<<<(N_NODES + 7) / 8, 256>>>(b2, out);
}